// round 9
// baseline (speedup 1.0000x reference)
#include <cuda_runtime.h>
#include <cstdint>

// LatticeSnake: B=32, L=512, W=9. Output [B, L, 9,9,9, 1] fp32 (48 MB).
// Doubled walk coords (the 2(L-1) grid offset cancels):
//   residue j:   p = 2*idx[j],         v = acids[j]*mask[j]
//   midpoint k:  p = idx[k]+idx[k+1],  v = (acids[k]+acids[k+1]+1)*mask[k+1]
//   voxel (i,r): value = sum of points at p == 2*idx[i] + r - 4
//
// R9 = R8 gather-grid + VECTORIZED output stores:
//   gather treats the CTA's 11664-float slice as 2916 float4; per float4 one
//   index decomposition + 4 scalar grid LDS (incremental cell walk with
//   predicated rollovers) + ONE STG.128.  Cuts gather STG warp-ops 4x
//   (STG.32@5cyc -> STG.128@12cyc per 4 elems), attacking the MIO/LSU floor.

#define LS_L    512
#define LS_W    9
#define LS_W3   729
#define LS_R    16               // windows per CTA
#define LS_NT   256
#define LS_NG   (LS_L / LS_R)    // 32 groups per batch
#define LS_M    (2 * LS_L - 1)   // 1023 snake points
#define GRIDPAD 6912             // >= worst-case vol 19^3 = 6859, mult of 4

__global__ __launch_bounds__(LS_NT, 7)
void lattice_snake_kernel(const float* __restrict__ acids,
                          const float* __restrict__ mask,
                          const int*   __restrict__ idx,
                          float*       __restrict__ out)
{
    __shared__ alignas(16) float grid[GRIDPAD];   // 27648 B
    __shared__ short sidx[LS_L * 3];              //  3072 B (coords, int16)
    __shared__ int   sAw[LS_R];                   // per-window grid base cell
    __shared__ int   sBB[6];                      // gxl,gyl,gzl,sx,sy,sz

    const int b   = blockIdx.x >> 5;            // / LS_NG
    const int g   = blockIdx.x & (LS_NG - 1);
    const int i0  = g * LS_R;
    const int tid = threadIdx.x;

    const int*   gi = idx   + (size_t)b * LS_L * 3;
    const float* ga = acids + (size_t)b * LS_L;
    const float* gm = mask  + (size_t)b * LS_L;
    float* gout = out + (size_t)(b * LS_L + i0) * LS_W3;

    // ---- zero full worst-case grid ----
    {
        float4* g4 = reinterpret_cast<float4*>(grid);
        const float4 z = make_float4(0.f, 0.f, 0.f, 0.f);
        #pragma unroll
        for (int e = tid; e < GRIDPAD / 4; e += LS_NT) g4[e] = z;
    }

    if (tid < 32) {
        // ---- warp 0: bbox over 16 centers + per-window base cells ----
        const int r  = tid & 15;                 // lanes 16-31 duplicate
        const int jj = 3 * (i0 + r);
        const int cx = 2 * gi[jj + 0];
        const int cy = 2 * gi[jj + 1];
        const int cz = 2 * gi[jj + 2];
        int xmin = cx, xmax = cx, ymin = cy, ymax = cy, zmin = cz, zmax = cz;
        #pragma unroll
        for (int d = 8; d >= 1; d >>= 1) {
            xmin = min(xmin, __shfl_xor_sync(0xffffffffu, xmin, d));
            xmax = max(xmax, __shfl_xor_sync(0xffffffffu, xmax, d));
            ymin = min(ymin, __shfl_xor_sync(0xffffffffu, ymin, d));
            ymax = max(ymax, __shfl_xor_sync(0xffffffffu, ymax, d));
            zmin = min(zmin, __shfl_xor_sync(0xffffffffu, zmin, d));
            zmax = max(zmax, __shfl_xor_sync(0xffffffffu, zmax, d));
        }
        const int syv = ymax - ymin + 9;
        const int szv = zmax - zmin + 9;
        if (tid < 16)
            sAw[tid] = ((cx - xmin) * syv + (cy - ymin)) * szv + (cz - zmin);
        if (tid == 0) {
            sBB[0] = xmin - 4; sBB[1] = ymin - 4; sBB[2] = zmin - 4;
            sBB[3] = xmax - xmin + 9; sBB[4] = syv; sBB[5] = szv;
        }
    } else {
        // ---- warps 1-7: stage coords to int16 smem ----
        for (int e = tid - 32; e < LS_L * 3; e += LS_NT - 32)
            sidx[e] = (short)gi[e];
    }
    __syncthreads();

    const int gxl = sBB[0], gyl = sBB[1], gzl = sBB[2];
    const int sx  = sBB[3], sy  = sBB[4], sz  = sBB[5];

    // ---- scan 1023 points; bbox hits accumulate into grid ----
    #pragma unroll
    for (int rnd = 0; rnd < 4; rnd++) {
        const int j = tid + rnd * LS_NT;
        if (j < LS_M) {
            int px, py, pz;
            int k = j;
            if (j < LS_L) {
                const int jj = 3 * j;
                px = 2 * (int)sidx[jj + 0];
                py = 2 * (int)sidx[jj + 1];
                pz = 2 * (int)sidx[jj + 2];
            } else {
                k = j - LS_L;                    // 0 .. L-2
                const int jj = 3 * k;
                px = (int)sidx[jj + 0] + (int)sidx[jj + 3];
                py = (int)sidx[jj + 1] + (int)sidx[jj + 4];
                pz = (int)sidx[jj + 2] + (int)sidx[jj + 5];
            }
            const unsigned ux = (unsigned)(px - gxl);
            const unsigned uy = (unsigned)(py - gyl);
            const unsigned uz = (unsigned)(pz - gzl);
            if (ux < (unsigned)sx && uy < (unsigned)sy && uz < (unsigned)sz) {
                const float v = (j < LS_L)
                    ? ga[k] * gm[k]
                    : (ga[k] + ga[k + 1] + 1.0f) * gm[k + 1];
                atomicAdd(&grid[(ux * sy + uy) * sz + uz], v);
            }
        }
    }
    __syncthreads();   // grid complete

    // ---- gather, vectorized: per float4 -> 4 grid LDS + one STG.128 ----
    float4* gout4 = reinterpret_cast<float4*>(gout);
    const int dy = sz - LS_W;                 // row rollover delta (z wrap)
    const int dx = (sy - LS_W) * sz;          // plane rollover delta (y wrap)
    for (int f4 = tid; f4 < (LS_R * LS_W3) / 4; f4 += LS_NT) {
        const int e0  = f4 << 2;
        int w   = e0 / LS_W3;                 // magic-mul division
        int lin = e0 - w * LS_W3;
        int rx  = lin / 81;
        int rem = lin - rx * 81;
        int ry  = rem / 9;
        int rz  = rem - ry * 9;
        int cell = sAw[w] + (rx * sy + ry) * sz + rz;

        float4 o;
        o.x = grid[cell];
        #pragma unroll
        for (int q = 1; q < 4; q++) {
            rz++; cell++;
            if (rz == LS_W) {
                rz = 0; ry++; cell += dy;
                if (ry == LS_W) {
                    ry = 0; rx++; cell += dx;
                    if (rx == LS_W) { rx = 0; w++; cell = sAw[w]; }
                }
            }
            const float val = grid[cell];
            if (q == 1) o.y = val;
            else if (q == 2) o.z = val;
            else o.w = val;
        }
        gout4[f4] = o;
    }
}

extern "C" void kernel_launch(void* const* d_in, const int* in_sizes, int n_in,
                              void* d_out, int out_size)
{
    const float* acids = (const float*)d_in[0];   // [B, L]
    const float* mask  = (const float*)d_in[1];   // [B, L]
    const int*   idx   = (const int*)  d_in[2];   // [B, L, 3]
    float*       out   = (float*)d_out;           // [B, L, 9,9,9, 1]

    const int nB = in_sizes[0] / LS_L;            // 32
    lattice_snake_kernel<<<nB * LS_NG, LS_NT>>>(acids, mask, idx, out);
}

// round 10
// speedup vs baseline: 1.1214x; 1.1214x over previous
#include <cuda_runtime.h>
#include <cstdint>

// LatticeSnake: B=32, L=512, W=9. Output [B, L, 9,9,9, 1] fp32 (48 MB).
// Doubled walk coords (the 2(L-1) grid offset cancels):
//   residue j:   p = 2*idx[j],         v = acids[j]*mask[j]
//   midpoint k:  p = idx[k]+idx[k+1],  v = (acids[k]+acids[k+1]+1)*mask[k+1]
//   voxel (i,r): value = sum of points at p == 2*idx[i] + r - 4
//
// R10 = R8 gather-grid + TMA BULK STORES:
//   gather writes to a ping-pong smem staging slab (STS.32 ~1cyc/warp-op),
//   then cp.async.bulk.global.shared::cta.bulk_group pushes each 4-window
//   slab (11664 B, 16-aligned) to GMEM via the TMA engine -- the 48 MB of
//   output stores leave the LSU entirely and overlap other CTAs' compute.
//   Dynamic smem 55 KB: grid 28K | stage 2x11664 | sAw/sBB | coords int16.

#define LS_L    512
#define LS_W    9
#define LS_W3   729
#define LS_R    16               // windows per CTA
#define LS_NT   256
#define LS_NG   (LS_L / LS_R)    // 32 groups per batch
#define LS_M    (2 * LS_L - 1)   // 1023 snake points
#define GRID_F  7168             // >= worst-case vol 19^3 = 6859 (floats)
#define STAGE_F (4 * LS_W3)      // 2916 floats = 11664 B per slab
#define SM_GRID_B   0
#define SM_STAGE_B  (GRID_F * 4)                  // 28672
#define SM_AW_B     (SM_STAGE_B + 2 * STAGE_F * 4) // 52000 (16-aligned)
#define SM_BB_B     (SM_AW_B + LS_R * 4)           // 52064
#define SM_SIDX_B   (SM_BB_B + 6 * 4)              // 52088
#define SM_TOTAL_B  (SM_SIDX_B + LS_L * 3 * 2)     // 55160

__device__ __forceinline__ uint32_t ls_smem_u32(const void* p) {
    uint32_t a;
    asm("{ .reg .u64 t; cvta.to.shared.u64 t, %1; cvt.u32.u64 %0, t; }"
        : "=r"(a) : "l"(p));
    return a;
}

__global__ __launch_bounds__(LS_NT)
void lattice_snake_kernel(const float* __restrict__ acids,
                          const float* __restrict__ mask,
                          const int*   __restrict__ idx,
                          float*       __restrict__ out)
{
    extern __shared__ char smem_raw[];
    float* grid  = reinterpret_cast<float*>(smem_raw + SM_GRID_B);
    float* stage = reinterpret_cast<float*>(smem_raw + SM_STAGE_B);
    int*   sAw   = reinterpret_cast<int*>(smem_raw + SM_AW_B);
    int*   sBB   = reinterpret_cast<int*>(smem_raw + SM_BB_B);
    short* sidx  = reinterpret_cast<short*>(smem_raw + SM_SIDX_B);

    const int b   = blockIdx.x >> 5;            // / LS_NG
    const int g   = blockIdx.x & (LS_NG - 1);
    const int i0  = g * LS_R;
    const int tid = threadIdx.x;

    const int*   gi = idx   + (size_t)b * LS_L * 3;
    const float* ga = acids + (size_t)b * LS_L;
    const float* gm = mask  + (size_t)b * LS_L;
    float* gout = out + (size_t)(b * LS_L + i0) * LS_W3;

    // ---- zero full worst-case grid ----
    {
        float4* g4 = reinterpret_cast<float4*>(grid);
        const float4 z = make_float4(0.f, 0.f, 0.f, 0.f);
        #pragma unroll
        for (int e = tid; e < GRID_F / 4; e += LS_NT) g4[e] = z;
    }

    if (tid < 32) {
        // ---- warp 0: bbox over 16 centers + per-window base cells ----
        const int r  = tid & 15;                 // lanes 16-31 duplicate
        const int jj = 3 * (i0 + r);
        const int cx = 2 * gi[jj + 0];
        const int cy = 2 * gi[jj + 1];
        const int cz = 2 * gi[jj + 2];
        int xmin = cx, xmax = cx, ymin = cy, ymax = cy, zmin = cz, zmax = cz;
        #pragma unroll
        for (int d = 8; d >= 1; d >>= 1) {
            xmin = min(xmin, __shfl_xor_sync(0xffffffffu, xmin, d));
            xmax = max(xmax, __shfl_xor_sync(0xffffffffu, xmax, d));
            ymin = min(ymin, __shfl_xor_sync(0xffffffffu, ymin, d));
            ymax = max(ymax, __shfl_xor_sync(0xffffffffu, ymax, d));
            zmin = min(zmin, __shfl_xor_sync(0xffffffffu, zmin, d));
            zmax = max(zmax, __shfl_xor_sync(0xffffffffu, zmax, d));
        }
        const int syv = ymax - ymin + 9;
        const int szv = zmax - zmin + 9;
        if (tid < 16)
            sAw[tid] = ((cx - xmin) * syv + (cy - ymin)) * szv + (cz - zmin);
        if (tid == 0) {
            sBB[0] = xmin - 4; sBB[1] = ymin - 4; sBB[2] = zmin - 4;
            sBB[3] = xmax - xmin + 9; sBB[4] = syv; sBB[5] = szv;
        }
    } else {
        // ---- warps 1-7: stage coords to int16 smem ----
        for (int e = tid - 32; e < LS_L * 3; e += LS_NT - 32)
            sidx[e] = (short)gi[e];
    }
    __syncthreads();

    const int gxl = sBB[0], gyl = sBB[1], gzl = sBB[2];
    const int sx  = sBB[3], sy  = sBB[4], sz  = sBB[5];

    // ---- scan 1023 points; bbox hits accumulate into grid ----
    #pragma unroll
    for (int rnd = 0; rnd < 4; rnd++) {
        const int j = tid + rnd * LS_NT;
        if (j < LS_M) {
            int px, py, pz;
            int k = j;
            if (j < LS_L) {
                const int jj = 3 * j;
                px = 2 * (int)sidx[jj + 0];
                py = 2 * (int)sidx[jj + 1];
                pz = 2 * (int)sidx[jj + 2];
            } else {
                k = j - LS_L;                    // 0 .. L-2
                const int jj = 3 * k;
                px = (int)sidx[jj + 0] + (int)sidx[jj + 3];
                py = (int)sidx[jj + 1] + (int)sidx[jj + 4];
                pz = (int)sidx[jj + 2] + (int)sidx[jj + 5];
            }
            const unsigned ux = (unsigned)(px - gxl);
            const unsigned uy = (unsigned)(py - gyl);
            const unsigned uz = (unsigned)(pz - gzl);
            if (ux < (unsigned)sx && uy < (unsigned)sy && uz < (unsigned)sz) {
                const float v = (j < LS_L)
                    ? ga[k] * gm[k]
                    : (ga[k] + ga[k + 1] + 1.0f) * gm[k + 1];
                atomicAdd(&grid[(ux * sy + uy) * sz + uz], v);
            }
        }
    }

    // per-thread voxel decomposition (reused across all 16 windows)
    int relOff0, relOff1, relOff2;
    {
        #pragma unroll
        for (int kk = 0; kk < 3; kk++) {
            const int lin = tid + kk * LS_NT;
            const int rx  = lin / 81;
            const int rem = lin - rx * 81;
            const int ry  = rem / 9;
            const int rz  = rem - ry * 9;
            const int off = (rx * sy + ry) * sz + rz;
            if (kk == 0) relOff0 = off;
            else if (kk == 1) relOff1 = off;
            else relOff2 = off;
        }
    }
    __syncthreads();   // grid complete

    // ---- gather -> smem slab -> TMA bulk store (4 windows per slab) ----
    const uint32_t stage_sa = ls_smem_u32(stage);
    const bool k2ok = tid < (LS_W3 - 2 * LS_NT);   // 217
    #pragma unroll
    for (int grp = 0; grp < 4; grp++) {
        if (grp >= 2) {
            // slab buffer reuse: previous copy from this buffer must be done
            if (tid == 0)
                asm volatile("cp.async.bulk.wait_group 1;" ::: "memory");
            __syncthreads();
        }
        float* sb = stage + (grp & 1) * STAGE_F;
        #pragma unroll
        for (int wl = 0; wl < 4; wl++) {
            const int Aw = sAw[grp * 4 + wl];      // broadcast LDS
            float* row = sb + wl * LS_W3;
            row[tid]            = grid[Aw + relOff0];
            row[tid + LS_NT]    = grid[Aw + relOff1];
            if (k2ok) row[tid + 2 * LS_NT] = grid[Aw + relOff2];
        }
        __syncthreads();   // slab complete, visible to issuing thread
        if (tid == 0) {
            asm volatile("fence.proxy.async.shared::cta;" ::: "memory");
            asm volatile(
                "cp.async.bulk.global.shared::cta.bulk_group [%0], [%1], %2;"
                :: "l"(gout + grp * STAGE_F),
                   "r"(stage_sa + (grp & 1) * (STAGE_F * 4)),
                   "r"((unsigned)(STAGE_F * 4))
                : "memory");
            asm volatile("cp.async.bulk.commit_group;" ::: "memory");
        }
    }
    // all bulk copies must complete before smem is released
    if (tid == 0)
        asm volatile("cp.async.bulk.wait_group 0;" ::: "memory");
}

extern "C" void kernel_launch(void* const* d_in, const int* in_sizes, int n_in,
                              void* d_out, int out_size)
{
    const float* acids = (const float*)d_in[0];   // [B, L]
    const float* mask  = (const float*)d_in[1];   // [B, L]
    const int*   idx   = (const int*)  d_in[2];   // [B, L, 3]
    float*       out   = (float*)d_out;           // [B, L, 9,9,9, 1]

    cudaFuncSetAttribute(lattice_snake_kernel,
                         cudaFuncAttributeMaxDynamicSharedMemorySize,
                         SM_TOTAL_B);

    const int nB = in_sizes[0] / LS_L;            // 32
    lattice_snake_kernel<<<nB * LS_NG, LS_NT, SM_TOTAL_B>>>(acids, mask, idx, out);
}